// round 3
// baseline (speedup 1.0000x reference)
#include <cuda_runtime.h>
#include <cstdint>

// RoIAlign via per-(ROI, 4-channel) shared-memory staging.
// features: (B=2, C=256, H=200, W=200) f32 NCHW
// rois:     (N, 5) f32  [batch_idx, x1, y1, x2, y2]
// out:      (N, 256, 7, 7) f32
// SPATIAL_SCALE = 1/16, SAMPLING_RATIO = 2, POOLED = 7x7

#define POOLED 7
#define SCALE  0.0625f
#define CH     256
#define FH     200
#define FW     200
#define CPB    4                 // channels per block
#define NSAMP  (POOLED * 2)      // 14 sample positions per axis
// Region: roi span <= 40 px scaled, corners add <=3 -> <=43 per axis.
#define PSMAX  (43 * 43 + 2)     // per-channel smem plane (incl. odd-pad)

struct AxisInterp {
    int   lo;
    int   hi;
    float fr;
    bool  valid;
};

__device__ __forceinline__ AxisInterp interp_axis(float coord, int size)
{
    AxisInterp r;
    r.valid = (coord >= -1.0f) && (coord <= (float)size);
    float c  = fmaxf(coord, 0.0f);
    int lo   = min((int)floorf(c), size - 1);
    r.lo = lo;
    r.hi = min(lo + 1, size - 1);
    r.fr = (lo >= size - 1) ? 0.0f : (c - (float)lo);
    return r;
}

__global__ __launch_bounds__(256)
void roi_align_staged(const float* __restrict__ features,
                      const float* __restrict__ rois,
                      float* __restrict__ out)
{
    __shared__ int   s_yoL[NSAMP], s_yoH[NSAMP];   // premultiplied by RWs
    __shared__ int   s_xoL[NSAMP], s_xoH[NSAMP];
    __shared__ float s_wyH[NSAMP], s_wyL[NSAMP];
    __shared__ float s_wxH[NSAMP], s_wxL[NSAMP];
    __shared__ float region[CPB * PSMAX];

    const int blk = blockIdx.x;
    const int n   = blk >> 6;              // CH/CPB = 64 groups
    const int cg  = (blk & 63) * CPB;
    const int tid = threadIdx.x;

    // ---- per-ROI scalars (computed redundantly by every thread) ----
    const float* roi = rois + n * 5;
    const int   b  = (int)__ldg(&roi[0]);
    const float x1 = __ldg(&roi[1]) * SCALE;
    const float y1 = __ldg(&roi[2]) * SCALE;
    const float x2 = __ldg(&roi[3]) * SCALE;
    const float y2 = __ldg(&roi[4]) * SCALE;

    const float bin_w = fmaxf(x2 - x1, 1.0f) * (1.0f / POOLED);
    const float bin_h = fmaxf(y2 - y1, 1.0f) * (1.0f / POOLED);

    // sample s (0..13): pos = origin + (s_ph + 0.25 + 0.5*s_sub) * bin
    // positions are monotonically increasing in s, so bounds come from s=0 / s=13.
    const float yfirst = fmaf(0.25f,                 bin_h, y1);
    const float ylast  = fmaf((POOLED - 1) + 0.75f,  bin_h, y1);
    const float xfirst = fmaf(0.25f,                 bin_w, x1);
    const float xlast  = fmaf((POOLED - 1) + 0.75f,  bin_w, x1);

    const int y0   = interp_axis(yfirst, FH).lo;
    const int yend = interp_axis(ylast,  FH).hi;
    const int x0   = interp_axis(xfirst, FW).lo;
    const int xend = interp_axis(xlast,  FW).hi;

    const int RH  = yend - y0 + 1;
    const int RW  = xend - x0 + 1;
    const int RWs = RW | 1;                       // odd row stride (bank spread)
    int PS        = RH * RWs;
    PS += 1 + (PS & 1);                           // odd plane stride, >= RH*RWs+1

    // ---- per-ROI interpolation tables (threads 0..27) ----
    if (tid < 2 * NSAMP) {
        const int  s     = (tid < NSAMP) ? tid : tid - NSAMP;
        const bool is_y  = (tid < NSAMP);
        const int  ph    = s >> 1;
        const int  sub   = s & 1;
        const float t    = (float)ph + 0.25f + 0.5f * (float)sub;
        const float pos  = is_y ? fmaf(t, bin_h, y1) : fmaf(t, bin_w, x1);
        AxisInterp ai    = interp_axis(pos, is_y ? FH : FW);
        const float wH   = ai.valid ? (1.0f - ai.fr) : 0.0f;
        const float wL   = ai.valid ? ai.fr          : 0.0f;
        if (is_y) {
            s_yoL[s] = (ai.lo - y0) * RWs;
            s_yoH[s] = (ai.hi - y0) * RWs;
            s_wyH[s] = wH;
            s_wyL[s] = wL;
        } else {
            s_xoL[s] = ai.lo - x0;
            s_xoH[s] = ai.hi - x0;
            s_wxH[s] = wH;
            s_wxL[s] = wL;
        }
    }

    // ---- stage the feature region for CPB channels (coalesced rows) ----
    {
        const float* __restrict__ base =
            features + ((size_t)b * CH + cg) * (FH * FW) + y0 * FW + x0;
        const int total = RH * RW;
        for (int i = tid; i < total; i += 256) {
            const int y  = i / RW;
            const int x  = i - y * RW;
            const int go = y * FW + x;
            const int so = y * RWs + x;
#pragma unroll
            for (int c = 0; c < CPB; c++)
                region[c * PS + so] = __ldg(base + c * (FH * FW) + go);
        }
    }

    __syncthreads();

    // ---- compute: 4 channels x 49 bins = 196 outputs ----
    if (tid < CPB * POOLED * POOLED) {
        const int c   = tid / 49;
        const int bin = tid - c * 49;
        const int ph  = bin / 7;
        const int pw  = bin - ph * 7;

        const float* __restrict__ rg = region + c * PS;

        float acc = 0.0f;
#pragma unroll
        for (int sy = 0; sy < 2; sy++) {
            const int   s  = ph * 2 + sy;
            const int   oL = s_yoL[s];
            const int   oH = s_yoH[s];
            const float hy = s_wyH[s];
            const float ly = s_wyL[s];
#pragma unroll
            for (int sx = 0; sx < 2; sx++) {
                const int   t  = pw * 2 + sx;
                const int   xL = s_xoL[t];
                const int   xH = s_xoH[t];
                const float hx = s_wxH[t];
                const float lx = s_wxL[t];
                const float top = fmaf(lx, rg[oL + xH], hx * rg[oL + xL]);
                const float bot = fmaf(lx, rg[oH + xH], hx * rg[oH + xL]);
                acc = fmaf(hy, top, fmaf(ly, bot, acc));
            }
        }
        out[((size_t)n * CH + cg + c) * 49 + bin] = acc * 0.25f;
    }
}

extern "C" void kernel_launch(void* const* d_in, const int* in_sizes, int n_in,
                              void* d_out, int out_size)
{
    const float* features = (const float*)d_in[0];
    const float* rois     = (const float*)d_in[1];
    float*       out      = (float*)d_out;

    const int n_rois = in_sizes[1] / 5;            // 512
    const int blocks = n_rois * (CH / CPB);        // 32768

    roi_align_staged<<<blocks, 256>>>(features, rois, out);
}

// round 5
// speedup vs baseline: 2.4259x; 2.4259x over previous
#include <cuda_runtime.h>
#include <cstdint>

// RoIAlign, warp-cooperative: one warp handles (roi n, ph, 16-channel group).
// Lane = pw(7) x sx(2) x corner(2) = 28 active lanes; each lane owns one
// x-corner column. Per channel: 4 single-row LDGs + 4 FMA + shuffle reduce.
//
// features: (B=2, C=256, H=200, W=200) f32 NCHW
// rois:     (N, 5) f32  [batch_idx, x1, y1, x2, y2]
// out:      (N, 256, 7, 7) f32
// SPATIAL_SCALE = 1/16, SAMPLING_RATIO = 2, POOLED = 7x7

#define POOLED 7
#define SCALE  0.0625f
#define CH     256
#define FH     200
#define FW     200
#define CPW    16              // channels per warp
#define NCG    (CH / CPW)      // 16 channel groups

__global__ __launch_bounds__(256)
void roi_align_warp(const float* __restrict__ features,
                    const float* __restrict__ rois,
                    float* __restrict__ out)
{
    const int lane = threadIdx.x & 31;
    const int wid  = blockIdx.x * (blockDim.x >> 5) + (threadIdx.x >> 5);

    // wid = (n*NCG + cg)*7 + ph  (ph fastest: consecutive warps share rows in L1)
    const int ph = wid % POOLED;
    const int t  = wid / POOLED;
    const int cg = t % NCG;
    const int n  = t / NCG;

    // ---- per-ROI scalars (uniform across warp) ----
    const float* roi = rois + n * 5;
    const int   b  = (int)__ldg(&roi[0]);
    const float x1 = __ldg(&roi[1]) * SCALE;
    const float y1 = __ldg(&roi[2]) * SCALE;
    const float x2 = __ldg(&roi[3]) * SCALE;
    const float y2 = __ldg(&roi[4]) * SCALE;

    const float bin_w = fmaxf(x2 - x1, 1.0f) * (1.0f / POOLED);
    const float bin_h = fmaxf(y2 - y1, 1.0f) * (1.0f / POOLED);

    // ---- lane's x-corner column + weight (computed once) ----
    const int pw     = min(lane >> 2, POOLED - 1);  // lanes 28-31 duplicate pw=6
    const int sx     = (lane >> 1) & 1;
    const int corner = lane & 1;

    float wx;
    int   xc;
    {
        const float x  = fmaf((float)pw + 0.25f + 0.5f * (float)sx, bin_w, x1);
        const bool  vx = (x >= -1.0f) && (x <= (float)FW);
        const float cx = fmaxf(x, 0.0f);
        const int   lo = min((int)floorf(cx), FW - 1);
        const int   hi = min(lo + 1, FW - 1);
        const float fx = (lo >= FW - 1) ? 0.0f : (cx - (float)lo);
        xc = corner ? hi : lo;
        wx = corner ? fx : (1.0f - fx);
        if (!vx) wx = 0.0f;
    }

    // ---- y interpolation for the 2 samples of this ph (uniform) ----
    int   yrow[4];
    float wy[4];
#pragma unroll
    for (int sy = 0; sy < 2; sy++) {
        const float y  = fmaf((float)ph + 0.25f + 0.5f * (float)sy, bin_h, y1);
        const bool  vy = (y >= -1.0f) && (y <= (float)FH);
        const float cy = fmaxf(y, 0.0f);
        const int   lo = min((int)floorf(cy), FH - 1);
        const int   hi = min(lo + 1, FH - 1);
        const float fy = (lo >= FH - 1) ? 0.0f : (cy - (float)lo);
        yrow[2 * sy]     = lo;
        yrow[2 * sy + 1] = hi;
        wy[2 * sy]       = vy ? (1.0f - fy) : 0.0f;
        wy[2 * sy + 1]   = vy ? fy          : 0.0f;
    }

    // Combined per-lane tap weights (x * y), premultiplied by mean factor 1/4.
    const float w0 = 0.25f * wx * wy[0];
    const float w1 = 0.25f * wx * wy[1];
    const float w2 = 0.25f * wx * wy[2];
    const float w3 = 0.25f * wx * wy[3];

    const size_t plane = (size_t)FH * FW;
    const float* base  = features + ((size_t)b * CH + cg * CPW) * plane + xc;
    const float* p0 = base + yrow[0] * FW;
    const float* p1 = base + yrow[1] * FW;
    const float* p2 = base + yrow[2] * FW;
    const float* p3 = base + yrow[3] * FW;

    size_t     obase    = ((size_t)n * CH + (size_t)cg * CPW) * 49
                          + ph * POOLED + (lane >> 2);
    const bool do_store = ((lane & 3) == 0) && (lane < 4 * POOLED);

#pragma unroll
    for (int c = 0; c < CPW; c++) {
        float v =      w0 * __ldg(p0);
        v = fmaf(w1, __ldg(p1), v);
        v = fmaf(w2, __ldg(p2), v);
        v = fmaf(w3, __ldg(p3), v);
        // reduce over corner (xor 1) and sx (xor 2): lane 4k holds the bin sum
        v += __shfl_xor_sync(0xffffffffu, v, 1);
        v += __shfl_xor_sync(0xffffffffu, v, 2);
        if (do_store) out[obase] = v;
        p0 += plane; p1 += plane; p2 += plane; p3 += plane;
        obase += 49;
    }
}

extern "C" void kernel_launch(void* const* d_in, const int* in_sizes, int n_in,
                              void* d_out, int out_size)
{
    const float* features = (const float*)d_in[0];
    const float* rois     = (const float*)d_in[1];
    float*       out      = (float*)d_out;

    const int n_rois      = in_sizes[1] / 5;                 // 512
    const int total_warps = n_rois * NCG * POOLED;           // 57344
    const int wpb         = 8;                               // 256 threads
    const int blocks      = (total_warps + wpb - 1) / wpb;   // 7168

    roi_align_warp<<<blocks, wpb * 32>>>(features, rois, out);
}